// round 2
// baseline (speedup 1.0000x reference)
#include <cuda_runtime.h>
#include <cstdint>

// Problem constants (fixed by setup_inputs)
#define BT 4
#define NV 20000
#define NF 40000
#define HH 256
#define WW 256
#define SS 2048
#define VCAP 20480            // NV padded to multiple of TILE
#define TILE 2048             // verts per shared tile (32KB of float4)
#define MASK_PENALTY 1000.0f
#define BIGW 3.0e37f

// Scratch (no dynamic allocation allowed)
__device__ unsigned char g_visible[BT * NV];
__device__ float4        g_vert4[BT * VCAP];
__device__ int           g_hasInv[BT];

// ---------------------------------------------------------------------------
// K1: clear visibility flags, per-batch invisible flags, and the output scalar
// ---------------------------------------------------------------------------
__global__ void k_clear(float* out) {
    int i = blockIdx.x * blockDim.x + threadIdx.x;
    uint32_t* p = (uint32_t*)g_visible;          // BT*NV = 80000 bytes = 20000 words
    if (i < (BT * NV) / 4) p[i] = 0u;
    if (i < BT) g_hasInv[i] = 0;
    if (i == 0) out[0] = 0.0f;
}

// ---------------------------------------------------------------------------
// K2: visibility scatter. For every valid pixel, mark the 3 vertices of the
// referenced face. Plain byte stores (all writes are 1 -> race-free).
// NOTE: faces / pix_to_face are int32 in memory (JAX x64 disabled).
// ---------------------------------------------------------------------------
__global__ void k_vis(const int* __restrict__ p2f,
                      const int* __restrict__ faces) {
    int p = blockIdx.x * blockDim.x + threadIdx.x;
    if (p >= BT * HH * WW) return;
    int fi = p2f[p];
    if ((unsigned)fi >= (unsigned)(BT * NF)) return;   // also rejects -1
    int b  = fi / NF;
    const int* fr = faces + fi * 3;
    int base = b * NV;
    int v0 = fr[0], v1 = fr[1], v2 = fr[2];
    if ((unsigned)v0 < (unsigned)NV) g_visible[base + v0] = 1;
    if ((unsigned)v1 < (unsigned)NV) g_visible[base + v1] = 1;
    if ((unsigned)v2 < (unsigned)NV) g_visible[base + v2] = 1;
}

// ---------------------------------------------------------------------------
// K3: transform verts -> float4 {x, y, z, w} with w = 0.5*|v|^2 if visible,
// else BIGW (so invisible verts never win the min). Padding rows get BIGW too.
// Also record whether any real vertex is invisible (plain store, race-free).
// ---------------------------------------------------------------------------
__global__ void k_xform(const float* __restrict__ verts) {
    int i = blockIdx.x * blockDim.x + threadIdx.x;
    if (i >= BT * VCAP) return;
    int b = i / VCAP;
    int v = i - b * VCAP;
    float4 o;
    if (v < NV) {
        int idx = (b * NV + v) * 3;
        float x = verts[idx + 0];
        float y = verts[idx + 1];
        float z = verts[idx + 2];
        bool vis = (g_visible[b * NV + v] != 0);
        o = make_float4(x, y, z, vis ? 0.5f * (x * x + y * y + z * z) : BIGW);
        if (!vis) g_hasInv[b] = 1;
    } else {
        o = make_float4(0.f, 0.f, 0.f, BIGW);
    }
    g_vert4[i] = o;
}

// ---------------------------------------------------------------------------
// K4: main fused min-distance + masked sum.
// Grid: 128 blocks = BT(4) x 32 sample-groups. Block: 256 threads (8 warps).
// Each block handles 64 samples (lane l holds samples g*64+l and g*64+32+l).
// The 8 warps split each vert tile (256 rows/warp); lanes broadcast-read the
// same vert and update per-sample running mins of score = w - s.v.
// d2 = 2*score + |s|^2 (same expansion the reference uses).
// ---------------------------------------------------------------------------
__global__ void __launch_bounds__(256)
k_main(const float* __restrict__ bds, float* __restrict__ out) {
    __shared__ float4 sv[TILE];
    __shared__ float  sred[8][64];

    const int bx   = blockIdx.x;          // 0..127
    const int b    = bx >> 5;             // batch
    const int g    = bx & 31;             // sample group
    const int t    = threadIdx.x;
    const int wid  = t >> 5;
    const int lane = t & 31;

    const float4* bp = ((const float4*)bds) + b * SS;
    const int s0 = g * 64 + lane;
    const int s1 = s0 + 32;
    const float4 smp0 = bp[s0];
    const float4 smp1 = bp[s1];
    const float nsx0 = -smp0.x, nsy0 = -smp0.y, nsz0 = -smp0.z;
    const float nsx1 = -smp1.x, nsy1 = -smp1.y, nsz1 = -smp1.z;

    float m0a = BIGW, m0b = BIGW, m1a = BIGW, m1b = BIGW;

    const float4* vb = g_vert4 + b * VCAP;

    for (int tb = 0; tb < VCAP; tb += TILE) {
        // cooperative tile load (coalesced float4)
        #pragma unroll
        for (int j = 0; j < TILE / 256; j++)
            sv[t + j * 256] = vb[tb + t + j * 256];
        __syncthreads();

        const int base = wid * 256;
        #pragma unroll 4
        for (int i = 0; i < 256; i += 2) {
            float4 va = sv[base + i];
            float4 vc = sv[base + i + 1];
            m0a = fminf(m0a, fmaf(va.x, nsx0, fmaf(va.y, nsy0, fmaf(va.z, nsz0, va.w))));
            m1a = fminf(m1a, fmaf(va.x, nsx1, fmaf(va.y, nsy1, fmaf(va.z, nsz1, va.w))));
            m0b = fminf(m0b, fmaf(vc.x, nsx0, fmaf(vc.y, nsy0, fmaf(vc.z, nsz0, vc.w))));
            m1b = fminf(m1b, fmaf(vc.x, nsx1, fmaf(vc.y, nsy1, fmaf(vc.z, nsz1, vc.w))));
        }
        __syncthreads();   // protect sv before next tile's overwrite
    }

    sred[wid][lane]      = fminf(m0a, m0b);
    sred[wid][lane + 32] = fminf(m1a, m1b);
    __syncthreads();

    if (t < 64) {
        float mm = sred[0][t];
        #pragma unroll
        for (int w = 1; w < 8; w++) mm = fminf(mm, sred[w][t]);

        float4 sm = bp[g * 64 + t];
        float ss = sm.x * sm.x + sm.y * sm.y + sm.z * sm.z;
        float dist = 2.0f * mm + ss;
        if (g_hasInv[b]) dist = fminf(dist, MASK_PENALTY);
        float val = dist * sm.w;   // sample mask (0/1)

        // reduce 64 values (two warps) then atomicAdd
        #pragma unroll
        for (int off = 16; off; off >>= 1)
            val += __shfl_down_sync(0xffffffffu, val, off);
        if ((t & 31) == 0)
            atomicAdd(out, val * (1.0f / BT));
    }
}

// ---------------------------------------------------------------------------
// Launch
// Inputs (metadata order): verts f32, bds f32, faces int32, pix_to_face int32,
// n_samples (ignored; fixed = 2048). Output: scalar f32.
// ---------------------------------------------------------------------------
extern "C" void kernel_launch(void* const* d_in, const int* in_sizes, int n_in,
                              void* d_out, int out_size) {
    const float* verts = (const float*)d_in[0];
    const float* bds   = (const float*)d_in[1];
    const int*   faces = (const int*)d_in[2];
    const int*   p2f   = (const int*)d_in[3];
    float* out = (float*)d_out;

    k_clear<<<((BT * NV) / 4 + 255) / 256, 256>>>(out);
    k_vis<<<(BT * HH * WW + 255) / 256, 256>>>(p2f, faces);
    k_xform<<<(BT * VCAP + 255) / 256, 256>>>(verts);
    k_main<<<BT * 32, 256>>>(bds, out);
}

// round 3
// speedup vs baseline: 1.0925x; 1.0925x over previous
#include <cuda_runtime.h>
#include <cstdint>

// Problem constants (fixed by setup_inputs)
#define BT 4
#define NV 20000
#define NF 40000
#define HH 256
#define WW 256
#define SS 2048
#define VCAP 20480            // NV padded to multiple of (VS*TILE)
#define VS 4                  // vert splits per (batch, sample-group)
#define SG 16                 // sample groups (128 samples each)
#define VPB (VCAP / VS)       // 5120 verts per block
#define TILE 1280             // verts per shared tile (20KB of float4)
#define MASK_PENALTY 1000.0f
#define BIGW 3.0e37f

// Scratch (no dynamic allocation allowed)
__device__ unsigned char g_visible[BT * NV];
__device__ float4        g_vert4[BT * VCAP];
__device__ int           g_hasInv[BT];
__device__ float         g_part[VS * BT * SS];   // partial mins of score

// ---------------------------------------------------------------------------
// K1: clear visibility flags and per-batch invisible flags
// ---------------------------------------------------------------------------
__global__ void k_clear() {
    int i = blockIdx.x * blockDim.x + threadIdx.x;
    uint32_t* p = (uint32_t*)g_visible;          // BT*NV = 80000 bytes = 20000 words
    if (i < (BT * NV) / 4) p[i] = 0u;
    if (i < BT) g_hasInv[i] = 0;
}

// ---------------------------------------------------------------------------
// K2: visibility scatter. For every valid pixel, mark the 3 vertices of the
// referenced face. Plain byte stores (all writes are 1 -> race-free).
// faces / pix_to_face are int32 in memory (JAX x64 disabled).
// ---------------------------------------------------------------------------
__global__ void k_vis(const int* __restrict__ p2f,
                      const int* __restrict__ faces) {
    int p = blockIdx.x * blockDim.x + threadIdx.x;
    if (p >= BT * HH * WW) return;
    int fi = p2f[p];
    if ((unsigned)fi >= (unsigned)(BT * NF)) return;   // also rejects -1
    int b  = fi / NF;
    const int* fr = faces + fi * 3;
    int base = b * NV;
    int v0 = fr[0], v1 = fr[1], v2 = fr[2];
    if ((unsigned)v0 < (unsigned)NV) g_visible[base + v0] = 1;
    if ((unsigned)v1 < (unsigned)NV) g_visible[base + v1] = 1;
    if ((unsigned)v2 < (unsigned)NV) g_visible[base + v2] = 1;
}

// ---------------------------------------------------------------------------
// K3: transform verts -> float4 {x, y, z, w} with w = 0.5*|v|^2 if visible,
// else BIGW (so invisible verts never win the min). Padding rows get BIGW too.
// ---------------------------------------------------------------------------
__global__ void k_xform(const float* __restrict__ verts) {
    int i = blockIdx.x * blockDim.x + threadIdx.x;
    if (i >= BT * VCAP) return;
    int b = i / VCAP;
    int v = i - b * VCAP;
    float4 o;
    if (v < NV) {
        int idx = (b * NV + v) * 3;
        float x = verts[idx + 0];
        float y = verts[idx + 1];
        float z = verts[idx + 2];
        bool vis = (g_visible[b * NV + v] != 0);
        o = make_float4(x, y, z, vis ? 0.5f * (x * x + y * y + z * z) : BIGW);
        if (!vis) g_hasInv[b] = 1;
    } else {
        o = make_float4(0.f, 0.f, 0.f, BIGW);
    }
    g_vert4[i] = o;
}

// ---------------------------------------------------------------------------
// K4: main fused min-score kernel.
// Grid: 256 blocks = VS(4) x BT(4) x SG(16). Block: 256 threads (8 warps).
// Each block: 128 samples (4 per lane: lane + 32*j) x 5120 verts.
// 8 warps split each vert tile (160 verts/warp); lanes broadcast-read the
// same vert and update per-sample running mins of score = w - s.v.
// Partial mins go to g_part; K5 finishes d2 = 2*score + |s|^2 and the sum.
// ---------------------------------------------------------------------------
__global__ void __launch_bounds__(256)
k_main(const float* __restrict__ bds) {
    __shared__ float4 sv[TILE];
    __shared__ float  sred[8][128];

    const int bx   = blockIdx.x;          // 0..255
    const int vs   = bx >> 6;             // 0..3
    const int b    = (bx >> 4) & 3;       // batch
    const int sg   = bx & 15;             // sample group of 128
    const int t    = threadIdx.x;
    const int wid  = t >> 5;
    const int lane = t & 31;

    const float4* bp = ((const float4*)bds) + b * SS + sg * 128;

    float nx[4], ny[4], nz[4], mA[4], mB[4];
    #pragma unroll
    for (int j = 0; j < 4; j++) {
        float4 s = bp[lane + 32 * j];
        nx[j] = -s.x; ny[j] = -s.y; nz[j] = -s.z;
        mA[j] = BIGW; mB[j] = BIGW;
    }

    const float4* vb = g_vert4 + b * VCAP + vs * VPB;

    for (int tb = 0; tb < VPB; tb += TILE) {
        // cooperative tile load (coalesced float4): 1280 / 256 = 5 each
        #pragma unroll
        for (int j = 0; j < TILE / 256; j++)
            sv[t + j * 256] = vb[tb + t + j * 256];
        __syncthreads();

        const float4* wv = sv + wid * (TILE / 8);   // 160 verts per warp
        #pragma unroll 4
        for (int i = 0; i < TILE / 8; i += 2) {
            float4 va = wv[i];
            float4 vc = wv[i + 1];
            #pragma unroll
            for (int j = 0; j < 4; j++)
                mA[j] = fminf(mA[j], fmaf(va.x, nx[j], fmaf(va.y, ny[j], fmaf(va.z, nz[j], va.w))));
            #pragma unroll
            for (int j = 0; j < 4; j++)
                mB[j] = fminf(mB[j], fmaf(vc.x, nx[j], fmaf(vc.y, ny[j], fmaf(vc.z, nz[j], vc.w))));
        }
        __syncthreads();   // protect sv before next tile's overwrite
    }

    #pragma unroll
    for (int j = 0; j < 4; j++)
        sred[wid][lane + 32 * j] = fminf(mA[j], mB[j]);
    __syncthreads();

    if (t < 128) {
        float mm = sred[0][t];
        #pragma unroll
        for (int w = 1; w < 8; w++) mm = fminf(mm, sred[w][t]);
        g_part[(vs * BT + b) * SS + sg * 128 + t] = mm;
    }
}

// ---------------------------------------------------------------------------
// K5: final reduce. Single block: min over VS partials, convert score -> d2,
// apply invisible-penalty and sample mask, sum, write out directly.
// ---------------------------------------------------------------------------
__global__ void __launch_bounds__(256)
k_red(const float* __restrict__ bds, float* __restrict__ out) {
    __shared__ float ssum[256];
    const int t = threadIdx.x;
    float acc = 0.0f;
    #pragma unroll 4
    for (int i = t; i < BT * SS; i += 256) {
        int b = i >> 11;                         // SS = 2048
        float m = g_part[i];                     // vs = 0 slice: (0*BT+b)*SS+s = i
        #pragma unroll
        for (int v = 1; v < VS; v++)
            m = fminf(m, g_part[v * BT * SS + i]);
        float4 sm = ((const float4*)bds)[i];
        float ss2 = sm.x * sm.x + sm.y * sm.y + sm.z * sm.z;
        float dist = 2.0f * m + ss2;
        if (g_hasInv[b]) dist = fminf(dist, MASK_PENALTY);
        acc += dist * sm.w;                      // sample mask (0/1)
    }
    ssum[t] = acc;
    __syncthreads();
    #pragma unroll
    for (int s = 128; s > 0; s >>= 1) {
        if (t < s) ssum[t] += ssum[t + s];
        __syncthreads();
    }
    if (t == 0) out[0] = ssum[0] * (1.0f / BT);
}

// ---------------------------------------------------------------------------
// Launch
// Inputs (metadata order): verts f32, bds f32, faces int32, pix_to_face int32,
// n_samples (ignored; fixed = 2048). Output: scalar f32.
// ---------------------------------------------------------------------------
extern "C" void kernel_launch(void* const* d_in, const int* in_sizes, int n_in,
                              void* d_out, int out_size) {
    const float* verts = (const float*)d_in[0];
    const float* bds   = (const float*)d_in[1];
    const int*   faces = (const int*)d_in[2];
    const int*   p2f   = (const int*)d_in[3];
    float* out = (float*)d_out;

    k_clear<<<((BT * NV) / 4 + 255) / 256, 256>>>();
    k_vis<<<(BT * HH * WW + 255) / 256, 256>>>(p2f, faces);
    k_xform<<<(BT * VCAP + 255) / 256, 256>>>(verts);
    k_main<<<VS * BT * SG, 256>>>(bds);
    k_red<<<1, 256>>>(bds, out);
}

// round 4
// speedup vs baseline: 1.1727x; 1.0734x over previous
#include <cuda_runtime.h>
#include <cstdint>

// Problem constants (fixed by setup_inputs)
#define BT 4
#define NV 20000
#define NF 40000
#define HH 256
#define WW 256
#define SS 2048
#define VCAP 20480            // NV padded to multiple of VS*? (VS*VPB)
#define VS 16                 // vert splits
#define SG 8                  // sample groups (256 samples each, 8/lane)
#define VPB (VCAP / VS)       // 1280 verts per block = one tile
#define MASK_PENALTY 1000.0f
#define BIGW 3.0e37f

typedef unsigned long long u64;

// Scratch (no dynamic allocation allowed)
__device__ unsigned char g_visible[BT * NV];
__device__ u64           g_vert8[(size_t)BT * VCAP * 4];  // {x,x},{y,y},{z,z},{w,w}
__device__ int           g_hasInv[BT];
__device__ int           g_min[BT * SS];                  // encoded float mins

// ---- packed f32x2 helpers (sm_103a) ----
__device__ __forceinline__ u64 pack2(float lo, float hi) {
    u64 r; asm("mov.b64 %0, {%1, %2};" : "=l"(r) : "f"(lo), "f"(hi)); return r;
}
__device__ __forceinline__ void unpack2(u64 v, float& lo, float& hi) {
    asm("mov.b64 {%0, %1}, %2;" : "=f"(lo), "=f"(hi) : "l"(v));
}
__device__ __forceinline__ u64 fma2(u64 a, u64 b, u64 c) {
    u64 d; asm("fma.rn.f32x2 %0, %1, %2, %3;" : "=l"(d) : "l"(a), "l"(b), "l"(c)); return d;
}
__device__ __forceinline__ uint32_t smem_addr(const void* p) {
    return (uint32_t)__cvta_generic_to_shared(p);
}
// order-preserving float -> signed int map (involution)
__device__ __forceinline__ int enc(float f) {
    int k = __float_as_int(f);
    return k >= 0 ? k : (k ^ 0x7FFFFFFF);
}

// ---------------------------------------------------------------------------
// K1: clear visibility flags, hasInv flags, and init g_min to enc(BIGW)
// ---------------------------------------------------------------------------
__global__ void k_clear() {
    int i = blockIdx.x * blockDim.x + threadIdx.x;
    uint32_t* p = (uint32_t*)g_visible;          // BT*NV bytes = 20000 words
    if (i < (BT * NV) / 4) p[i] = 0u;
    if (i < BT * SS) g_min[i] = enc(BIGW);
    if (i < BT) g_hasInv[i] = 0;
}

// ---------------------------------------------------------------------------
// K2: visibility scatter (faces / pix_to_face are int32 in memory)
// ---------------------------------------------------------------------------
__global__ void k_vis(const int* __restrict__ p2f,
                      const int* __restrict__ faces) {
    int p = blockIdx.x * blockDim.x + threadIdx.x;
    if (p >= BT * HH * WW) return;
    int fi = p2f[p];
    if ((unsigned)fi >= (unsigned)(BT * NF)) return;   // also rejects -1
    int b  = fi / NF;
    const int* fr = faces + fi * 3;
    int base = b * NV;
    int v0 = fr[0], v1 = fr[1], v2 = fr[2];
    if ((unsigned)v0 < (unsigned)NV) g_visible[base + v0] = 1;
    if ((unsigned)v1 < (unsigned)NV) g_visible[base + v1] = 1;
    if ((unsigned)v2 < (unsigned)NV) g_visible[base + v2] = 1;
}

// ---------------------------------------------------------------------------
// K3: verts -> duplicated packed layout {x,x}{y,y}{z,z}{w,w},
// w = 0.5*|v|^2 if visible else BIGW; padding rows get BIGW.
// ---------------------------------------------------------------------------
__global__ void k_xform(const float* __restrict__ verts) {
    int i = blockIdx.x * blockDim.x + threadIdx.x;
    if (i >= BT * VCAP) return;
    int b = i / VCAP;
    int v = i - b * VCAP;
    float x = 0.f, y = 0.f, z = 0.f, w = BIGW;
    if (v < NV) {
        int idx = (b * NV + v) * 3;
        x = verts[idx + 0]; y = verts[idx + 1]; z = verts[idx + 2];
        bool vis = (g_visible[b * NV + v] != 0);
        if (vis) w = 0.5f * (x * x + y * y + z * z);
        else     g_hasInv[b] = 1;
    }
    u64* o = g_vert8 + (size_t)i * 4;
    o[0] = pack2(x, x); o[1] = pack2(y, y); o[2] = pack2(z, z); o[3] = pack2(w, w);
}

// ---------------------------------------------------------------------------
// K4: main fused min-score kernel (packed f32x2 math).
// Grid: 512 blocks = VS(16) x BT(4) x SG(8). Block: 256 threads (8 warps).
// Block: 256 samples (8/lane, as 4 packed pairs) x 1280 verts (one tile).
// Each warp scans 160 verts; score = w - s.v via 3 fma.f32x2 per sample-pair.
// Partial mins folded into g_min via order-preserving int atomicMin.
// ---------------------------------------------------------------------------
__global__ void __launch_bounds__(256)
k_main(const float* __restrict__ bds) {
    __shared__ __align__(16) u64 sv[VPB * 4];   // 40KB
    __shared__ float sred[8][256];              // 8KB

    const int bx   = blockIdx.x;          // 0..511
    const int vs   = bx & 15;
    const int b    = (bx >> 4) & 3;
    const int sg   = bx >> 6;              // 0..7
    const int t    = threadIdx.x;
    const int wid  = t >> 5;
    const int lane = t & 31;

    const float4* bp = ((const float4*)bds) + b * SS + sg * 256;

    u64 nx2[4], ny2[4], nz2[4];
    float mlo[4], mhi[4];
    #pragma unroll
    for (int p = 0; p < 4; p++) {
        float4 sa = bp[lane + 64 * p];         // sample j = 2p
        float4 sb = bp[lane + 64 * p + 32];    // sample j = 2p+1
        nx2[p] = pack2(-sa.x, -sb.x);
        ny2[p] = pack2(-sa.y, -sb.y);
        nz2[p] = pack2(-sa.z, -sb.z);
        mlo[p] = BIGW; mhi[p] = BIGW;
    }

    // cooperative tile load: VPB*4 u64 = 2560 uint4, 10 per thread
    {
        const uint4* src = (const uint4*)(g_vert8 + (size_t)(b * VCAP + vs * VPB) * 4);
        uint4* dst = (uint4*)sv;
        #pragma unroll
        for (int j = 0; j < 10; j++)
            dst[t + j * 256] = src[t + j * 256];
    }
    __syncthreads();

    uint32_t addr = smem_addr(sv) + (wid * 160) * 32;
    #pragma unroll 4
    for (int i = 0; i < 160; i++) {
        u64 xx, yy, zz, ww;
        asm volatile("ld.shared.v2.u64 {%0, %1}, [%2];"
                     : "=l"(xx), "=l"(yy) : "r"(addr));
        asm volatile("ld.shared.v2.u64 {%0, %1}, [%2];"
                     : "=l"(zz), "=l"(ww) : "r"(addr + 16));
        #pragma unroll
        for (int p = 0; p < 4; p++) {
            u64 acc = fma2(xx, nx2[p], fma2(yy, ny2[p], fma2(zz, nz2[p], ww)));
            float lo, hi; unpack2(acc, lo, hi);
            mlo[p] = fminf(mlo[p], lo);
            mhi[p] = fminf(mhi[p], hi);
        }
        addr += 32;
    }

    #pragma unroll
    for (int p = 0; p < 4; p++) {
        sred[wid][p * 64 + lane]      = mlo[p];
        sred[wid][p * 64 + 32 + lane] = mhi[p];
    }
    __syncthreads();

    // cross-warp min for sample (sg*256 + t), then global atomic fold
    {
        float mm = sred[0][t];
        #pragma unroll
        for (int w = 1; w < 8; w++) mm = fminf(mm, sred[w][t]);
        atomicMin(&g_min[b * SS + sg * 256 + t], enc(mm));
    }
}

// ---------------------------------------------------------------------------
// K5: final reduce. One block, 1024 threads: decode mins, d2 = 2*score+|s|^2,
// invisible penalty, sample mask, sum, write out.
// ---------------------------------------------------------------------------
__global__ void __launch_bounds__(1024)
k_red(const float* __restrict__ bds, float* __restrict__ out) {
    __shared__ float ssum[1024];
    const int t = threadIdx.x;
    float acc = 0.0f;
    #pragma unroll
    for (int k = 0; k < (BT * SS) / 1024; k++) {
        int i = t + k * 1024;
        int b = i >> 11;                         // SS = 2048
        int e = g_min[i];
        float m = __int_as_float(e >= 0 ? e : (e ^ 0x7FFFFFFF));
        float4 sm = ((const float4*)bds)[i];
        float ss2 = sm.x * sm.x + sm.y * sm.y + sm.z * sm.z;
        float dist = 2.0f * m + ss2;
        if (g_hasInv[b]) dist = fminf(dist, MASK_PENALTY);
        acc += dist * sm.w;                      // sample mask (0/1)
    }
    ssum[t] = acc;
    __syncthreads();
    #pragma unroll
    for (int s = 512; s > 0; s >>= 1) {
        if (t < s) ssum[t] += ssum[t + s];
        __syncthreads();
    }
    if (t == 0) out[0] = ssum[0] * (1.0f / BT);
}

// ---------------------------------------------------------------------------
// Launch
// Inputs (metadata order): verts f32, bds f32, faces int32, pix_to_face int32,
// n_samples (ignored; fixed = 2048). Output: scalar f32.
// ---------------------------------------------------------------------------
extern "C" void kernel_launch(void* const* d_in, const int* in_sizes, int n_in,
                              void* d_out, int out_size) {
    const float* verts = (const float*)d_in[0];
    const float* bds   = (const float*)d_in[1];
    const int*   faces = (const int*)d_in[2];
    const int*   p2f   = (const int*)d_in[3];
    float* out = (float*)d_out;

    k_clear<<<((BT * NV) / 4 + 255) / 256, 256>>>();
    k_vis<<<(BT * HH * WW + 255) / 256, 256>>>(p2f, faces);
    k_xform<<<(BT * VCAP + 255) / 256, 256>>>(verts);
    k_main<<<VS * BT * SG, 256>>>(bds);
    k_red<<<1, 1024>>>(bds, out);
}